// round 14
// baseline (speedup 1.0000x reference)
#include <cuda_runtime.h>
#include <cuda_bf16.h>

// Problem constants (shapes are fixed by the dataset).
#define FH   200
#define FW   304
#define FC   256
#define FC3  768
#define H1   100
#define W1   152
#define H2   50
#define W2   76
#define OUTH 7
#define OUTW 7
#define NBINS 49   // 7*7
#define NSAMP 14   // 7*2 sample coords per axis

// Fused feature map in HWC layout: g_fused[h][w][c], c fastest. ~187 MB.
__device__ float g_fused[FH * FW * FC3];

// -------------------------------------------------------------------------
// Kernel 1: fuse (copy / bilinear-upsample) + transpose CHW -> HWC.
// Grid: x = ceil(FW/32)=10, y = FH=200, z = 24 (channel tiles of 32 over 768).
// Block: 32x32. tile[ty][tx] = value(channel ct*32+ty, h, w0+tx); write
// transposed so channel becomes the fast axis.
// -------------------------------------------------------------------------
__global__ void __launch_bounds__(1024) fuse_kernel(
    const float* __restrict__ f0,
    const float* __restrict__ f1,
    const float* __restrict__ f2)
{
    __shared__ float tile[32][33];
    const int tx = threadIdx.x, ty = threadIdx.y;
    const int h  = blockIdx.y;
    const int w0 = blockIdx.x << 5;
    const int ct = blockIdx.z;            // 0..23 -> global channel tile
    const int lvl = ct >> 3;              // 0,1,2
    const int cl  = ((ct & 7) << 5) + ty; // channel within level (read)
    const int w   = w0 + tx;

    float v = 0.0f;
    if (w < FW) {
        if (lvl == 0) {
            v = f0[(cl * FH + h) * FW + w];
        } else if (lvl == 1) {
            // half-pixel x2 upsample: src = (dst+0.5)/2 - 0.5
            float ys = 0.5f * (float)h - 0.25f;
            float xs = 0.5f * (float)w - 0.25f;
            float yf = floorf(ys), xf = floorf(xs);
            float fy = ys - yf,   fx = xs - xf;
            int iy0 = max((int)yf, 0);
            int ix0 = max((int)xf, 0);
            int iy1 = min((int)yf + 1, H1 - 1);
            int ix1 = min((int)xf + 1, W1 - 1);
            const float* b = f1 + cl * (H1 * W1);
            float v00 = b[iy0 * W1 + ix0], v01 = b[iy0 * W1 + ix1];
            float v10 = b[iy1 * W1 + ix0], v11 = b[iy1 * W1 + ix1];
            v = (1.0f - fy) * ((1.0f - fx) * v00 + fx * v01)
              +         fy  * ((1.0f - fx) * v10 + fx * v11);
        } else {
            // half-pixel x4 upsample: src = (dst+0.5)/4 - 0.5
            float ys = 0.25f * (float)h - 0.375f;
            float xs = 0.25f * (float)w - 0.375f;
            float yf = floorf(ys), xf = floorf(xs);
            float fy = ys - yf,   fx = xs - xf;
            int iy0 = max((int)yf, 0);
            int ix0 = max((int)xf, 0);
            int iy1 = min((int)yf + 1, H2 - 1);
            int ix1 = min((int)xf + 1, W2 - 1);
            const float* b = f2 + cl * (H2 * W2);
            float v00 = b[iy0 * W2 + ix0], v01 = b[iy0 * W2 + ix1];
            float v10 = b[iy1 * W2 + ix0], v11 = b[iy1 * W2 + ix1];
            v = (1.0f - fy) * ((1.0f - fx) * v00 + fx * v01)
              +         fy  * ((1.0f - fx) * v10 + fx * v11);
        }
    }
    tile[ty][tx] = v;
    __syncthreads();

    // write: channel = ct*32 + tx (fast), w = w0 + ty
    const int wq = w0 + ty;
    if (wq < FW) {
        g_fused[(h * FW + wq) * FC3 + (ct << 5) + tx] = tile[tx][ty];
    }
}

// -------------------------------------------------------------------------
// Robust scalar decode: works for int32, little-endian int64, or float32.
// -------------------------------------------------------------------------
__device__ __forceinline__ float decode_dim(const void* p) {
    int iv = *(const int*)p;
    if (iv > 0 && iv < 1000000) return (float)iv;   // int32 / low word of int64
    float fv = __int_as_float(iv);
    if (fv > 0.0f && fv < 1000000.0f) return fv;    // float32
    return (float)iv;
}

// -------------------------------------------------------------------------
// Kernel 2: RoIAlign over the fused HWC map.
// Grid: (6 channel-chunks of 128, N boxes). Block: 256 threads.
//   t & 31  -> float4 channel group (32 groups * 4 = 128 channels)
//   t >> 5  -> bin slice (8 slices over 49 bins)
// Accumulates into smem in output [c][bin] order, then block-copies
// contiguously to d_out (coalesced stores).
// -------------------------------------------------------------------------
__global__ void __launch_bounds__(256) roi_kernel(
    const float* __restrict__ boxes,
    const void*  __restrict__ pimh,
    const void*  __restrict__ pimw,
    float* __restrict__ out)
{
    const int chunk = blockIdx.x;   // 0..5
    const int n     = blockIdx.y;   // box
    const int cbase = chunk << 7;   // *128

    __shared__ __align__(16) float acc[128 * NBINS];   // 25088 B
    __shared__ int   sy0[NSAMP], sy1c[NSAMP], sx0[NSAMP], sx1c[NSAMP];
    __shared__ float shy[NSAMP], sly[NSAMP], shx[NSAMP], slx[NSAMP];

    const int t = threadIdx.x;

    if (t < 2 * NSAMP) {
        const bool isY = (t < NSAMP);
        const int  j   = isY ? t : t - NSAMP;
        const float dimImg  = isY ? decode_dim(pimh) : decode_dim(pimw);
        const float dimFeat = isY ? (float)FH : (float)FW;
        const float scale = dimFeat / dimImg;
        const float lo = boxes[n * 4 + (isY ? 1 : 0)] * scale;
        const float hi = boxes[n * 4 + (isY ? 3 : 2)] * scale;
        const float sz    = fmaxf(hi - lo, 1.0f);
        const float binsz = sz * (1.0f / 7.0f);
        const int   o = j >> 1, r = j & 1;
        const float coord = lo + ((float)o + 0.25f + 0.5f * (float)r) * binsz;
        const bool  valid = (coord >= -1.0f) && (coord <= dimFeat);
        const float cc = fminf(fmaxf(coord, 0.0f), dimFeat - 1.0f);
        const int   i0 = (int)floorf(cc);
        const int   i1 = min(i0 + 1, (int)dimFeat - 1);
        float l  = cc - (float)i0;
        float hw = 1.0f - l;
        if (!valid) { l = 0.0f; hw = 0.0f; }   // fold validity into weights
        if (isY) { sy0[j] = i0; sy1c[j] = i1; shy[j] = hw; sly[j] = l; }
        else     { sx0[j] = i0; sx1c[j] = i1; shx[j] = hw; slx[j] = l; }
    }
    __syncthreads();

    const int cg    = t & 31;
    const int slice = t >> 5;
    const int cAbs  = cbase + (cg << 2);
    const float4* __restrict__ f4 = reinterpret_cast<const float4*>(g_fused);

    for (int bin = slice; bin < NBINS; bin += 8) {
        const int oh = bin / 7;
        const int ow = bin - oh * 7;
        float ax = 0.0f, ay = 0.0f, az = 0.0f, aw = 0.0f;

        #pragma unroll
        for (int ry = 0; ry < 2; ry++) {
            const int jy = (oh << 1) + ry;
            const int y0 = sy0[jy], y1 = sy1c[jy];
            const float hy = shy[jy], ly = sly[jy];
            const int rowA = (y0 * FW);
            const int rowB = (y1 * FW);
            #pragma unroll
            for (int rx = 0; rx < 2; rx++) {
                const int jx = (ow << 1) + rx;
                const int x0 = sx0[jx], x1 = sx1c[jx];
                const float hx = shx[jx], lx = slx[jx];
                const float w00 = hy * hx, w01 = hy * lx;
                const float w10 = ly * hx, w11 = ly * lx;
                const float4 v00 = f4[(((rowA + x0) * FC3) + cAbs) >> 2];
                const float4 v01 = f4[(((rowA + x1) * FC3) + cAbs) >> 2];
                const float4 v10 = f4[(((rowB + x0) * FC3) + cAbs) >> 2];
                const float4 v11 = f4[(((rowB + x1) * FC3) + cAbs) >> 2];
                ax += w00 * v00.x + w01 * v01.x + w10 * v10.x + w11 * v11.x;
                ay += w00 * v00.y + w01 * v01.y + w10 * v10.y + w11 * v11.y;
                az += w00 * v00.z + w01 * v01.z + w10 * v10.z + w11 * v11.z;
                aw += w00 * v00.w + w01 * v01.w + w10 * v10.w + w11 * v11.w;
            }
        }
        // mean over the 2x2 sampling grid (always /4)
        const int cL = cg << 2;
        acc[(cL + 0) * NBINS + bin] = ax * 0.25f;
        acc[(cL + 1) * NBINS + bin] = ay * 0.25f;
        acc[(cL + 2) * NBINS + bin] = az * 0.25f;
        acc[(cL + 3) * NBINS + bin] = aw * 0.25f;
    }
    __syncthreads();

    // Contiguous, coalesced copy of this (box, chunk) slab: 128*49 floats.
    const float4* s4 = reinterpret_cast<const float4*>(acc);
    float4* o4 = reinterpret_cast<float4*>(out + (size_t)n * (FC3 * NBINS) + cbase * NBINS);
    #pragma unroll 4
    for (int i = t; i < (128 * NBINS) / 4; i += 256) {
        o4[i] = s4[i];
    }
}

// -------------------------------------------------------------------------
// Launch. Inputs (metadata order): feat0, feat1, feat2, boxes, img_h, img_w.
// -------------------------------------------------------------------------
extern "C" void kernel_launch(void* const* d_in, const int* in_sizes, int n_in,
                              void* d_out, int out_size)
{
    const float* f0    = (const float*)d_in[0];
    const float* f1    = (const float*)d_in[1];
    const float* f2    = (const float*)d_in[2];
    const float* boxes = (const float*)d_in[3];
    const void*  pimh  = d_in[4];
    const void*  pimw  = d_in[5];
    const int N = in_sizes[3] / 4;

    dim3 b1(32, 32);
    dim3 g1((FW + 31) / 32, FH, FC3 / 32);
    fuse_kernel<<<g1, b1>>>(f0, f1, f2);

    dim3 g2(FC3 / 128, N);   // chunk fastest -> same-box blocks adjacent (L2 locality)
    roi_kernel<<<g2, 256>>>(boxes, pimh, pimw, (float*)d_out);
}

// round 15
// speedup vs baseline: 1.9676x; 1.9676x over previous
#include <cuda_runtime.h>
#include <cuda_fp16.h>
#include <cuda_bf16.h>

// Problem constants (shapes are fixed by the dataset).
#define FH   200
#define FW   304
#define FC   256
#define FC3  768
#define H1   100
#define W1   152
#define H2   50
#define W2   76
#define OUTH 7
#define OUTW 7
#define NBINS 49   // 7*7
#define NSAMP 14   // 7*2 sample coords per axis

// Fused feature map in HWC layout, fp16: g_fused[h][w][c], c fastest. ~93 MB
// -> fits in L2 (126 MB), so the RoI gather phase is mostly L2-resident.
__device__ __align__(16) __half g_fused[FH * FW * FC3];

// -------------------------------------------------------------------------
// Kernel 1: fuse (copy / bilinear-upsample) + transpose CHW -> HWC(fp16).
// Grid: x = 12 (64-channel tiles, FASTEST -> concurrent blocks complete full
//       contiguous HWC pixel rows = dense DRAM writes), y = 10 (w tiles),
//       z = 200 (h).
// Block: 32x32; each thread covers 2 channels in the read phase.
// Write phase: warp = one w position, 32 threads x half2 = 64 channels
//       = 128 contiguous bytes per warp store.
// -------------------------------------------------------------------------
__global__ void __launch_bounds__(1024) fuse_kernel(
    const float* __restrict__ f0,
    const float* __restrict__ f1,
    const float* __restrict__ f2)
{
    __shared__ float tile[64][33];
    const int tx = threadIdx.x, ty = threadIdx.y;
    const int ct = blockIdx.x;            // 0..11 -> 64-channel tile
    const int w0 = blockIdx.y << 5;
    const int h  = blockIdx.z;
    const int lvl    = ct >> 2;           // 0,1,2
    const int clbase = (ct & 3) << 6;     // channel base within level
    const int w      = w0 + tx;

    float v0 = 0.0f, v1 = 0.0f;
    if (w < FW) {
        if (lvl == 0) {
            v0 = f0[((clbase + ty)      * FH + h) * FW + w];
            v1 = f0[((clbase + ty + 32) * FH + h) * FW + w];
        } else if (lvl == 1) {
            // half-pixel x2 upsample: src = (dst+0.5)/2 - 0.5
            float ys = 0.5f * (float)h - 0.25f;
            float xs = 0.5f * (float)w - 0.25f;
            float yf = floorf(ys), xf = floorf(xs);
            float fy = ys - yf,   fx = xs - xf;
            int iy0 = max((int)yf, 0);
            int ix0 = max((int)xf, 0);
            int iy1 = min((int)yf + 1, H1 - 1);
            int ix1 = min((int)xf + 1, W1 - 1);
            const float w00 = (1.0f - fy) * (1.0f - fx);
            const float w01 = (1.0f - fy) * fx;
            const float w10 = fy * (1.0f - fx);
            const float w11 = fy * fx;
            const float* a = f1 + (clbase + ty) * (H1 * W1);
            const float* b = a + 32 * (H1 * W1);
            v0 = w00 * a[iy0 * W1 + ix0] + w01 * a[iy0 * W1 + ix1]
               + w10 * a[iy1 * W1 + ix0] + w11 * a[iy1 * W1 + ix1];
            v1 = w00 * b[iy0 * W1 + ix0] + w01 * b[iy0 * W1 + ix1]
               + w10 * b[iy1 * W1 + ix0] + w11 * b[iy1 * W1 + ix1];
        } else {
            // half-pixel x4 upsample: src = (dst+0.5)/4 - 0.5
            float ys = 0.25f * (float)h - 0.375f;
            float xs = 0.25f * (float)w - 0.375f;
            float yf = floorf(ys), xf = floorf(xs);
            float fy = ys - yf,   fx = xs - xf;
            int iy0 = max((int)yf, 0);
            int ix0 = max((int)xf, 0);
            int iy1 = min((int)yf + 1, H2 - 1);
            int ix1 = min((int)xf + 1, W2 - 1);
            const float w00 = (1.0f - fy) * (1.0f - fx);
            const float w01 = (1.0f - fy) * fx;
            const float w10 = fy * (1.0f - fx);
            const float w11 = fy * fx;
            const float* a = f2 + (clbase + ty) * (H2 * W2);
            const float* b = a + 32 * (H2 * W2);
            v0 = w00 * a[iy0 * W2 + ix0] + w01 * a[iy0 * W2 + ix1]
               + w10 * a[iy1 * W2 + ix0] + w11 * a[iy1 * W2 + ix1];
            v1 = w00 * b[iy0 * W2 + ix0] + w01 * b[iy0 * W2 + ix1]
               + w10 * b[iy1 * W2 + ix0] + w11 * b[iy1 * W2 + ix1];
        }
    }
    tile[ty][tx]      = v0;
    tile[ty + 32][tx] = v1;
    __syncthreads();

    // write: channel pair = 2*tx (fast), w = w0 + ty
    const int wq = w0 + ty;
    if (wq < FW) {
        __half2 hv = __floats2half2_rn(tile[2 * tx][ty], tile[2 * tx + 1][ty]);
        *reinterpret_cast<__half2*>(
            &g_fused[(h * FW + wq) * FC3 + (ct << 6) + (tx << 1)]) = hv;
    }
}

// -------------------------------------------------------------------------
// Robust scalar decode: works for int32, little-endian int64, or float32.
// -------------------------------------------------------------------------
__device__ __forceinline__ float decode_dim(const void* p) {
    int iv = *(const int*)p;
    if (iv > 0 && iv < 1000000) return (float)iv;   // int32 / low word of int64
    float fv = __int_as_float(iv);
    if (fv > 0.0f && fv < 1000000.0f) return fv;    // float32
    return (float)iv;
}

struct h4 { __half2 a, b; };   // 4 contiguous fp16 channels (8 bytes)

// -------------------------------------------------------------------------
// Kernel 2: RoIAlign over the fused HWC fp16 map.
// Grid: (6 channel-chunks of 128, N boxes). Block: 256 threads.
//   t & 31  -> 4-channel group (32 groups * 4 = 128 channels)
//   t >> 5  -> bin slice (8 slices over 49 bins)
// Accumulates (fp32) into smem in output [c][bin] order, then block-copies
// contiguously to d_out (coalesced stores).
// -------------------------------------------------------------------------
__global__ void __launch_bounds__(256) roi_kernel(
    const float* __restrict__ boxes,
    const void*  __restrict__ pimh,
    const void*  __restrict__ pimw,
    float* __restrict__ out)
{
    const int chunk = blockIdx.x;   // 0..5
    const int n     = blockIdx.y;   // box
    const int cbase = chunk << 7;   // *128

    __shared__ __align__(16) float acc[128 * NBINS];   // 25088 B
    __shared__ int   sy0[NSAMP], sy1c[NSAMP], sx0[NSAMP], sx1c[NSAMP];
    __shared__ float shy[NSAMP], sly[NSAMP], shx[NSAMP], slx[NSAMP];

    const int t = threadIdx.x;

    if (t < 2 * NSAMP) {
        const bool isY = (t < NSAMP);
        const int  j   = isY ? t : t - NSAMP;
        const float dimImg  = isY ? decode_dim(pimh) : decode_dim(pimw);
        const float dimFeat = isY ? (float)FH : (float)FW;
        const float scale = dimFeat / dimImg;
        const float lo = boxes[n * 4 + (isY ? 1 : 0)] * scale;
        const float hi = boxes[n * 4 + (isY ? 3 : 2)] * scale;
        const float sz    = fmaxf(hi - lo, 1.0f);
        const float binsz = sz * (1.0f / 7.0f);
        const int   o = j >> 1, r = j & 1;
        const float coord = lo + ((float)o + 0.25f + 0.5f * (float)r) * binsz;
        const bool  valid = (coord >= -1.0f) && (coord <= dimFeat);
        const float cc = fminf(fmaxf(coord, 0.0f), dimFeat - 1.0f);
        const int   i0 = (int)floorf(cc);
        const int   i1 = min(i0 + 1, (int)dimFeat - 1);
        float l  = cc - (float)i0;
        float hw = 1.0f - l;
        if (!valid) { l = 0.0f; hw = 0.0f; }   // fold validity into weights
        if (isY) { sy0[j] = i0; sy1c[j] = i1; shy[j] = hw; sly[j] = l; }
        else     { sx0[j] = i0; sx1c[j] = i1; shx[j] = hw; slx[j] = l; }
    }
    __syncthreads();

    const int cg    = t & 31;
    const int slice = t >> 5;
    const int cAbs  = cbase + (cg << 2);
    const h4* __restrict__ fp = reinterpret_cast<const h4*>(g_fused);

    for (int bin = slice; bin < NBINS; bin += 8) {
        const int oh = bin / 7;
        const int ow = bin - oh * 7;
        float ax = 0.0f, ay = 0.0f, az = 0.0f, aw = 0.0f;

        #pragma unroll
        for (int ry = 0; ry < 2; ry++) {
            const int jy = (oh << 1) + ry;
            const int y0 = sy0[jy], y1 = sy1c[jy];
            const float hy = shy[jy], ly = sly[jy];
            const int rowA = (y0 * FW);
            const int rowB = (y1 * FW);
            #pragma unroll
            for (int rx = 0; rx < 2; rx++) {
                const int jx = (ow << 1) + rx;
                const int x0 = sx0[jx], x1 = sx1c[jx];
                const float hx = shx[jx], lx = slx[jx];
                const float w00 = hy * hx, w01 = hy * lx;
                const float w10 = ly * hx, w11 = ly * lx;
                const h4 v00 = fp[(((rowA + x0) * FC3) + cAbs) >> 2];
                const h4 v01 = fp[(((rowA + x1) * FC3) + cAbs) >> 2];
                const h4 v10 = fp[(((rowB + x0) * FC3) + cAbs) >> 2];
                const h4 v11 = fp[(((rowB + x1) * FC3) + cAbs) >> 2];
                const float2 a00 = __half22float2(v00.a), b00 = __half22float2(v00.b);
                const float2 a01 = __half22float2(v01.a), b01 = __half22float2(v01.b);
                const float2 a10 = __half22float2(v10.a), b10 = __half22float2(v10.b);
                const float2 a11 = __half22float2(v11.a), b11 = __half22float2(v11.b);
                ax += w00 * a00.x + w01 * a01.x + w10 * a10.x + w11 * a11.x;
                ay += w00 * a00.y + w01 * a01.y + w10 * a10.y + w11 * a11.y;
                az += w00 * b00.x + w01 * b01.x + w10 * b10.x + w11 * b11.x;
                aw += w00 * b00.y + w01 * b01.y + w10 * b10.y + w11 * b11.y;
            }
        }
        // mean over the 2x2 sampling grid (always /4)
        const int cL = cg << 2;
        acc[(cL + 0) * NBINS + bin] = ax * 0.25f;
        acc[(cL + 1) * NBINS + bin] = ay * 0.25f;
        acc[(cL + 2) * NBINS + bin] = az * 0.25f;
        acc[(cL + 3) * NBINS + bin] = aw * 0.25f;
    }
    __syncthreads();

    // Contiguous, coalesced copy of this (box, chunk) slab: 128*49 floats.
    const float4* s4 = reinterpret_cast<const float4*>(acc);
    float4* o4 = reinterpret_cast<float4*>(out + (size_t)n * (FC3 * NBINS) + cbase * NBINS);
    #pragma unroll 4
    for (int i = t; i < (128 * NBINS) / 4; i += 256) {
        o4[i] = s4[i];
    }
}

// -------------------------------------------------------------------------
// Launch. Inputs (metadata order): feat0, feat1, feat2, boxes, img_h, img_w.
// -------------------------------------------------------------------------
extern "C" void kernel_launch(void* const* d_in, const int* in_sizes, int n_in,
                              void* d_out, int out_size)
{
    const float* f0    = (const float*)d_in[0];
    const float* f1    = (const float*)d_in[1];
    const float* f2    = (const float*)d_in[2];
    const float* boxes = (const float*)d_in[3];
    const void*  pimh  = d_in[4];
    const void*  pimw  = d_in[5];
    const int N = in_sizes[3] / 4;

    // channel tile FASTEST: concurrent blocks complete full contiguous HWC
    // pixel rows -> dense DRAM write bursts instead of 128B fragments.
    dim3 b1(32, 32);
    dim3 g1(FC3 / 64, (FW + 31) / 32, FH);
    fuse_kernel<<<g1, b1>>>(f0, f1, f2);

    dim3 g2(FC3 / 128, N);   // chunk fastest -> same-box blocks adjacent (L2 locality)
    roi_kernel<<<g2, 256>>>(boxes, pimh, pimw, (float*)d_out);
}

// round 16
// speedup vs baseline: 2.9927x; 1.5210x over previous
#include <cuda_runtime.h>
#include <cuda_fp16.h>
#include <cuda_bf16.h>

// Problem constants (shapes are fixed by the dataset).
#define FH   200
#define FW   304
#define FC   256
#define FC3  768
#define H1   100
#define W1   152
#define H2   50
#define W2   76
#define OUTH 7
#define OUTW 7
#define NBINS 49   // 7*7
#define NSAMP 14   // 7*2 sample coords per axis
#define HTILE 4    // h rows per fuse block

// Fused feature map in HWC layout, fp16: g_fused[h][w][c], c fastest. ~93 MB.
__device__ __align__(16) __half g_fused[FH * FW * FC3];

// -------------------------------------------------------------------------
// Kernel 1: fuse (copy / bilinear-upsample) + transpose CHW -> HWC(fp16).
// Grid: x = 12 (64-ch tiles, fastest), y = 10 (w tiles of 32), z = 50 (h/4).
// Block: 32x8 = 256 threads; loops over 4 h rows and 8 channel rows.
// 6000 blocks * 256 thr -> ~8 CTA/SM occupancy, ~5 waves (vs 81 before).
// -------------------------------------------------------------------------
__global__ void __launch_bounds__(256) fuse_kernel(
    const float* __restrict__ f0,
    const float* __restrict__ f1,
    const float* __restrict__ f2)
{
    __shared__ float tile[64][33];
    const int tx = threadIdx.x;           // 0..31 -> w within tile (phase1) / ch pair (phase2)
    const int ty = threadIdx.y;           // 0..7
    const int ct = blockIdx.x;            // 0..11 -> 64-channel tile
    const int w0 = blockIdx.y << 5;
    const int h0 = blockIdx.z * HTILE;
    const int lvl    = ct >> 2;           // 0,1,2
    const int clbase = (ct & 3) << 6;     // channel base within level
    const int w      = w0 + tx;
    const bool wok   = (w < FW);

    // x-interp params (depend only on w) for upsample levels: hoist fully.
    int ix0 = 0, ix1 = 0;
    float fx = 0.0f;
    if (lvl == 1) {
        float xs = 0.5f * (float)w - 0.25f;
        float xf = floorf(xs);
        fx  = xs - xf;
        ix0 = max((int)xf, 0);
        ix1 = min((int)xf + 1, W1 - 1);
    } else if (lvl == 2) {
        float xs = 0.25f * (float)w - 0.375f;
        float xf = floorf(xs);
        fx  = xs - xf;
        ix0 = max((int)xf, 0);
        ix1 = min((int)xf + 1, W2 - 1);
    }

    for (int hh = 0; hh < HTILE; hh++) {
        const int h = h0 + hh;

        if (lvl == 0) {
            #pragma unroll
            for (int r = 0; r < 8; r++) {
                const int c = clbase + (r << 3) + ty;
                tile[(r << 3) + ty][tx] = wok ? f0[(c * FH + h) * FW + w] : 0.0f;
            }
        } else if (lvl == 1) {
            float ys = 0.5f * (float)h - 0.25f;
            float yf = floorf(ys);
            float fy = ys - yf;
            int iy0 = max((int)yf, 0);
            int iy1 = min((int)yf + 1, H1 - 1);
            const float w00 = (1.0f - fy) * (1.0f - fx);
            const float w01 = (1.0f - fy) * fx;
            const float w10 = fy * (1.0f - fx);
            const float w11 = fy * fx;
            const int o00 = iy0 * W1 + ix0, o01 = iy0 * W1 + ix1;
            const int o10 = iy1 * W1 + ix0, o11 = iy1 * W1 + ix1;
            #pragma unroll
            for (int r = 0; r < 8; r++) {
                const int c = clbase + (r << 3) + ty;
                const float* b = f1 + c * (H1 * W1);
                float v = w00 * b[o00] + w01 * b[o01] + w10 * b[o10] + w11 * b[o11];
                tile[(r << 3) + ty][tx] = wok ? v : 0.0f;
            }
        } else {
            float ys = 0.25f * (float)h - 0.375f;
            float yf = floorf(ys);
            float fy = ys - yf;
            int iy0 = max((int)yf, 0);
            int iy1 = min((int)yf + 1, H2 - 1);
            const float w00 = (1.0f - fy) * (1.0f - fx);
            const float w01 = (1.0f - fy) * fx;
            const float w10 = fy * (1.0f - fx);
            const float w11 = fy * fx;
            const int o00 = iy0 * W2 + ix0, o01 = iy0 * W2 + ix1;
            const int o10 = iy1 * W2 + ix0, o11 = iy1 * W2 + ix1;
            #pragma unroll
            for (int r = 0; r < 8; r++) {
                const int c = clbase + (r << 3) + ty;
                const float* b = f2 + c * (H2 * W2);
                float v = w00 * b[o00] + w01 * b[o01] + w10 * b[o10] + w11 * b[o11];
                tile[(r << 3) + ty][tx] = wok ? v : 0.0f;
            }
        }
        __syncthreads();

        // store phase: lane tx -> channel pair (2*tx, 2*tx+1); ty+8k -> w slot.
        // warp store = 32 lanes x half2 = 128 contiguous bytes.
        #pragma unroll
        for (int wl = ty; wl < 32; wl += 8) {
            const int wq = w0 + wl;
            if (wq < FW) {
                __half2 hv = __floats2half2_rn(tile[2 * tx][wl], tile[2 * tx + 1][wl]);
                *reinterpret_cast<__half2*>(
                    &g_fused[(h * FW + wq) * FC3 + (ct << 6) + (tx << 1)]) = hv;
            }
        }
        __syncthreads();
    }
}

// -------------------------------------------------------------------------
// Robust scalar decode: works for int32, little-endian int64, or float32.
// -------------------------------------------------------------------------
__device__ __forceinline__ float decode_dim(const void* p) {
    int iv = *(const int*)p;
    if (iv > 0 && iv < 1000000) return (float)iv;   // int32 / low word of int64
    float fv = __int_as_float(iv);
    if (fv > 0.0f && fv < 1000000.0f) return fv;    // float32
    return (float)iv;
}

struct h4 { __half2 a, b; };   // 4 contiguous fp16 channels (8 bytes)

// -------------------------------------------------------------------------
// Kernel 2: RoIAlign over the fused HWC fp16 map. (unchanged from R15)
// -------------------------------------------------------------------------
__global__ void __launch_bounds__(256) roi_kernel(
    const float* __restrict__ boxes,
    const void*  __restrict__ pimh,
    const void*  __restrict__ pimw,
    float* __restrict__ out)
{
    const int chunk = blockIdx.x;   // 0..5
    const int n     = blockIdx.y;   // box
    const int cbase = chunk << 7;   // *128

    __shared__ __align__(16) float acc[128 * NBINS];   // 25088 B
    __shared__ int   sy0[NSAMP], sy1c[NSAMP], sx0[NSAMP], sx1c[NSAMP];
    __shared__ float shy[NSAMP], sly[NSAMP], shx[NSAMP], slx[NSAMP];

    const int t = threadIdx.x;

    if (t < 2 * NSAMP) {
        const bool isY = (t < NSAMP);
        const int  j   = isY ? t : t - NSAMP;
        const float dimImg  = isY ? decode_dim(pimh) : decode_dim(pimw);
        const float dimFeat = isY ? (float)FH : (float)FW;
        const float scale = dimFeat / dimImg;
        const float lo = boxes[n * 4 + (isY ? 1 : 0)] * scale;
        const float hi = boxes[n * 4 + (isY ? 3 : 2)] * scale;
        const float sz    = fmaxf(hi - lo, 1.0f);
        const float binsz = sz * (1.0f / 7.0f);
        const int   o = j >> 1, r = j & 1;
        const float coord = lo + ((float)o + 0.25f + 0.5f * (float)r) * binsz;
        const bool  valid = (coord >= -1.0f) && (coord <= dimFeat);
        const float cc = fminf(fmaxf(coord, 0.0f), dimFeat - 1.0f);
        const int   i0 = (int)floorf(cc);
        const int   i1 = min(i0 + 1, (int)dimFeat - 1);
        float l  = cc - (float)i0;
        float hw = 1.0f - l;
        if (!valid) { l = 0.0f; hw = 0.0f; }   // fold validity into weights
        if (isY) { sy0[j] = i0; sy1c[j] = i1; shy[j] = hw; sly[j] = l; }
        else     { sx0[j] = i0; sx1c[j] = i1; shx[j] = hw; slx[j] = l; }
    }
    __syncthreads();

    const int cg    = t & 31;
    const int slice = t >> 5;
    const int cAbs  = cbase + (cg << 2);
    const h4* __restrict__ fp = reinterpret_cast<const h4*>(g_fused);

    for (int bin = slice; bin < NBINS; bin += 8) {
        const int oh = bin / 7;
        const int ow = bin - oh * 7;
        float ax = 0.0f, ay = 0.0f, az = 0.0f, aw = 0.0f;

        #pragma unroll
        for (int ry = 0; ry < 2; ry++) {
            const int jy = (oh << 1) + ry;
            const int y0 = sy0[jy], y1 = sy1c[jy];
            const float hy = shy[jy], ly = sly[jy];
            const int rowA = (y0 * FW);
            const int rowB = (y1 * FW);
            #pragma unroll
            for (int rx = 0; rx < 2; rx++) {
                const int jx = (ow << 1) + rx;
                const int x0 = sx0[jx], x1 = sx1c[jx];
                const float hx = shx[jx], lx = slx[jx];
                const float w00 = hy * hx, w01 = hy * lx;
                const float w10 = ly * hx, w11 = ly * lx;
                const h4 v00 = fp[(((rowA + x0) * FC3) + cAbs) >> 2];
                const h4 v01 = fp[(((rowA + x1) * FC3) + cAbs) >> 2];
                const h4 v10 = fp[(((rowB + x0) * FC3) + cAbs) >> 2];
                const h4 v11 = fp[(((rowB + x1) * FC3) + cAbs) >> 2];
                const float2 a00 = __half22float2(v00.a), b00 = __half22float2(v00.b);
                const float2 a01 = __half22float2(v01.a), b01 = __half22float2(v01.b);
                const float2 a10 = __half22float2(v10.a), b10 = __half22float2(v10.b);
                const float2 a11 = __half22float2(v11.a), b11 = __half22float2(v11.b);
                ax += w00 * a00.x + w01 * a01.x + w10 * a10.x + w11 * a11.x;
                ay += w00 * a00.y + w01 * a01.y + w10 * a10.y + w11 * a11.y;
                az += w00 * b00.x + w01 * b01.x + w10 * b10.x + w11 * b11.x;
                aw += w00 * b00.y + w01 * b01.y + w10 * b10.y + w11 * b11.y;
            }
        }
        // mean over the 2x2 sampling grid (always /4)
        const int cL = cg << 2;
        acc[(cL + 0) * NBINS + bin] = ax * 0.25f;
        acc[(cL + 1) * NBINS + bin] = ay * 0.25f;
        acc[(cL + 2) * NBINS + bin] = az * 0.25f;
        acc[(cL + 3) * NBINS + bin] = aw * 0.25f;
    }
    __syncthreads();

    // Contiguous, coalesced copy of this (box, chunk) slab: 128*49 floats.
    const float4* s4 = reinterpret_cast<const float4*>(acc);
    float4* o4 = reinterpret_cast<float4*>(out + (size_t)n * (FC3 * NBINS) + cbase * NBINS);
    #pragma unroll 4
    for (int i = t; i < (128 * NBINS) / 4; i += 256) {
        o4[i] = s4[i];
    }
}

// -------------------------------------------------------------------------
// Launch. Inputs (metadata order): feat0, feat1, feat2, boxes, img_h, img_w.
// -------------------------------------------------------------------------
extern "C" void kernel_launch(void* const* d_in, const int* in_sizes, int n_in,
                              void* d_out, int out_size)
{
    const float* f0    = (const float*)d_in[0];
    const float* f1    = (const float*)d_in[1];
    const float* f2    = (const float*)d_in[2];
    const float* boxes = (const float*)d_in[3];
    const void*  pimh  = d_in[4];
    const void*  pimw  = d_in[5];
    const int N = in_sizes[3] / 4;

    dim3 b1(32, 8);
    dim3 g1(FC3 / 64, (FW + 31) / 32, FH / HTILE);
    fuse_kernel<<<g1, b1>>>(f0, f1, f2);

    dim3 g2(FC3 / 128, N);   // chunk fastest -> same-box blocks adjacent (L2 locality)
    roi_kernel<<<g2, 256>>>(boxes, pimh, pimw, (float*)d_out);
}